// round 1
// baseline (speedup 1.0000x reference)
#include <cuda_runtime.h>
#include <math.h>

#define TPB 128
#define RPB 128          // rows per block tile
#define NC 99

// ---------------- scratch (device globals; no allocation) ----------------
__device__ unsigned int g_minmax[20];   // [0..9] min keys, [10..19] max keys
__device__ int          g_hist[202];    // [0..99] m-hist, [100..199] f-hist, [200]=m_count, [201]=f_count
__device__ float        g_part[2];      // [0]=mse_sum, [1]=ce_sum

// col -> code: 0..7 = CE block id, 8..11 = cont index (col 0,55,56,57)
__constant__ signed char c_code[99] = {
    8,                                   // 0
    0,0,0,0,0,0,0,                       // 1-7
    1,1,1,1,1,1,1,1,1,1,1,1,1,1,1,1,     // 8-23
    2,2,2,2,2,2,2,                       // 24-30
    3,3,3,3,3,3,3,3,3,3,3,3,3,3,         // 31-44
    4,4,4,4,4,4,                         // 45-50
    5,5,                                 // 51-52
    6,6,                                 // 53-54
    9,10,11,                             // 55-57
    7,7,7,7,7,7,7,7,7,7,7,7,7,7,7,7,7,7,7,7,7, // 58-78
    7,7,7,7,7,7,7,7,7,7,7,7,7,7,7,7,7,7,7,7    // 79-98
};

// monotonic float <-> uint key (total order preserved)
__device__ __forceinline__ unsigned fkey(float f) {
    unsigned u = __float_as_uint(f);
    return (u & 0x80000000u) ? ~u : (u | 0x80000000u);
}
__device__ __forceinline__ float kinv(unsigned k) {
    return __uint_as_float((k & 0x80000000u) ? (k & 0x7fffffffu) : ~k);
}

// ---------------- kernel 0: zero scratch (graph replay safe) ----------------
__global__ void k_init() {
    int t = threadIdx.x;
    if (t < 202) g_hist[t] = 0;
    if (t < 2)   g_part[t] = 0.0f;
    if (t < 10)       g_minmax[t] = 0xFFFFFFFFu;   // min slots
    else if (t < 20)  g_minmax[t] = 0u;            // max slots
}

// ---------------- kernel 1: per-feature min/max over encoded[:, 0:10] ----------------
__global__ void k_minmax(const float* __restrict__ enc, int B) {
    float mn[10], mx[10];
#pragma unroll
    for (int f = 0; f < 10; f++) { mn[f] = INFINITY; mx[f] = -INFINITY; }

    int stride = gridDim.x * blockDim.x;
    for (int r = blockIdx.x * blockDim.x + threadIdx.x; r < B; r += stride) {
        const float4* p = (const float4*)(enc + (size_t)r * 12);
        float4 a = p[0], b = p[1], c = p[2];
        mn[0] = fminf(mn[0], a.x); mx[0] = fmaxf(mx[0], a.x);
        mn[1] = fminf(mn[1], a.y); mx[1] = fmaxf(mx[1], a.y);
        mn[2] = fminf(mn[2], a.z); mx[2] = fmaxf(mx[2], a.z);
        mn[3] = fminf(mn[3], a.w); mx[3] = fmaxf(mx[3], a.w);
        mn[4] = fminf(mn[4], b.x); mx[4] = fmaxf(mx[4], b.x);
        mn[5] = fminf(mn[5], b.y); mx[5] = fmaxf(mx[5], b.y);
        mn[6] = fminf(mn[6], b.z); mx[6] = fmaxf(mx[6], b.z);
        mn[7] = fminf(mn[7], b.w); mx[7] = fmaxf(mx[7], b.w);
        mn[8] = fminf(mn[8], c.x); mx[8] = fmaxf(mx[8], c.x);
        mn[9] = fminf(mn[9], c.y); mx[9] = fmaxf(mx[9], c.y);
    }
#pragma unroll
    for (int f = 0; f < 10; f++) {
#pragma unroll
        for (int o = 16; o > 0; o >>= 1) {
            mn[f] = fminf(mn[f], __shfl_xor_sync(0xffffffffu, mn[f], o));
            mx[f] = fmaxf(mx[f], __shfl_xor_sync(0xffffffffu, mx[f], o));
        }
    }
    __shared__ float smn[8][10], smx[8][10];
    int w = threadIdx.x >> 5, lane = threadIdx.x & 31;
    if (lane == 0) {
#pragma unroll
        for (int f = 0; f < 10; f++) { smn[w][f] = mn[f]; smx[w][f] = mx[f]; }
    }
    __syncthreads();
    if (threadIdx.x < 10) {
        int f = threadIdx.x;
        float a = INFINITY, b = -INFINITY;
#pragma unroll
        for (int ww = 0; ww < 8; ww++) { a = fminf(a, smn[ww][f]); b = fmaxf(b, smx[ww][f]); }
        atomicMin(&g_minmax[f],      fkey(a));
        atomicMax(&g_minmax[10 + f], fkey(b));
    }
}

// ---------------- kernel 2: fused MSE + CE + histograms ----------------
// dyn smem layout (floats):
//   s_dec : RPB*99        (decoded tile)
//   s_enc : RPB*13        (encoded tile, pad 13 => conflict-free)
//   s_ct  : RPB*5         (cont-col true values, pad 5)
//   s_lab : RPB*9 ints    (one-hot label col per CE block, pad 9)
//   s_hist: 202 ints
//   s_red : 8 floats
#define SMEM_BYTES ((RPB*NC + RPB*13 + RPB*5) * 4 + (RPB*9 + 202) * 4 + 8 * 4)

__global__ void __launch_bounds__(TPB, 3) k_main(const float* __restrict__ enc,
                                                 const float* __restrict__ dec,
                                                 const float* __restrict__ tru) {
    extern __shared__ float sm[];
    float* s_dec  = sm;
    float* s_enc  = s_dec + RPB * NC;
    float* s_ct   = s_enc + RPB * 13;
    int*   s_lab  = (int*)(s_ct + RPB * 5);
    int*   s_hist = s_lab + RPB * 9;
    float* s_red  = (float*)(s_hist + 202);

    const int t = threadIdx.x;
    const size_t blk = blockIdx.x;
    const int bs[8] = {1, 8, 24, 31, 45, 51, 53, 58};
    const int be[8] = {8, 24, 31, 45, 51, 53, 55, 99};

    // ---- load decoded tile (contiguous rows -> linear, coalesced float4) ----
    const float4* dsrc = (const float4*)(dec + blk * (RPB * NC));
    float4* sdec4 = (float4*)s_dec;
    for (int i = t; i < (RPB * NC) / 4; i += TPB) sdec4[i] = dsrc[i];

    // ---- load encoded tile into pad-13 layout ----
    const float4* esrc = (const float4*)(enc + blk * (RPB * 12));
    for (int i = t; i < (RPB * 12) / 4; i += TPB) {
        float4 v = esrc[i];
        int e = 4 * i, r = e / 12, c = e - r * 12;   // c in {0,4,8}: no row wrap
        float* d = &s_enc[r * 13 + c];
        d[0] = v.x; d[1] = v.y; d[2] = v.z; d[3] = v.w;
    }

    // ---- init smem scratch ----
    for (int i = t; i < 202; i += TPB) s_hist[i] = 0;
#pragma unroll
    for (int b = 0; b < 8; b++) s_lab[t * 9 + b] = bs[b];
    __syncthreads();

    // ---- stream data_true: compress one-hots -> label col; keep cont values ----
    const float4* tsrc = (const float4*)(tru + blk * (RPB * NC));
    for (int i = t; i < (RPB * NC) / 4; i += TPB) {
        float4 v = tsrc[i];
        int e = 4 * i, r = e / 99, c = e - r * 99;
        float vv[4] = {v.x, v.y, v.z, v.w};
#pragma unroll
        for (int j = 0; j < 4; j++) {
            int code = c_code[c];
            if (code < 8) {
                if (vv[j] != 0.0f) s_lab[r * 9 + code] = c;
            } else {
                s_ct[r * 5 + (code - 8)] = vv[j];
            }
            if (++c == 99) { c = 0; ++r; }
        }
    }
    __syncthreads();

    // ---- per-row work: thread t owns row t of the tile ----
    const float* dr = &s_dec[t * NC];
    float ms, ce = 0.0f;
    {
        float d0 = dr[0]  - s_ct[t * 5 + 0];
        float d1 = dr[55] - s_ct[t * 5 + 1];
        float d2 = dr[56] - s_ct[t * 5 + 2];
        float d3 = dr[57] - s_ct[t * 5 + 3];
        ms = d0 * d0 + d1 * d1 + d2 * d2 + d3 * d3;
    }
#pragma unroll
    for (int b = 0; b < 8; b++) {
        float m = -INFINITY;
        for (int c = bs[b]; c < be[b]; c++) m = fmaxf(m, dr[c]);
        float sum = 0.0f;
        for (int c = bs[b]; c < be[b]; c++) sum += __expf(dr[c] - m);
        int lc = s_lab[t * 9 + b];
        ce += m + __logf(sum) - dr[lc];
    }

    // ---- histograms ----
    {
        float sex = s_enc[t * 13 + 11];
        int sel = (sex == 0.0f) ? 0 : ((sex == 1.0f) ? 1 : -1);
        if (sel >= 0) {
            atomicAdd(&s_hist[200 + sel], 1);
            float mnv[10], wv[10];
#pragma unroll
            for (int f = 0; f < 10; f++) {
                mnv[f] = kinv(g_minmax[f]);
                float mxv = kinv(g_minmax[10 + f]);
                wv[f] = fmaxf(mxv - mnv[f], 1e-12f);
            }
#pragma unroll
            for (int f = 0; f < 10; f++) {
                float u = (s_enc[t * 13 + f] - mnv[f]) / wv[f] * 10.0f;
                int bi = (int)floorf(u);
                bi = bi < 0 ? 0 : (bi > 9 ? 9 : bi);
                atomicAdd(&s_hist[sel * 100 + f * 10 + bi], 1);
            }
        }
    }

    // ---- block reduce mse/ce, flush hist ----
#pragma unroll
    for (int o = 16; o > 0; o >>= 1) {
        ms += __shfl_xor_sync(0xffffffffu, ms, o);
        ce += __shfl_xor_sync(0xffffffffu, ce, o);
    }
    int w = t >> 5, lane = t & 31;
    if (lane == 0) { s_red[w] = ms; s_red[4 + w] = ce; }
    __syncthreads();
    if (t == 0) {
        atomicAdd(&g_part[0], s_red[0] + s_red[1] + s_red[2] + s_red[3]);
        atomicAdd(&g_part[1], s_red[4] + s_red[5] + s_red[6] + s_red[7]);
    }
    for (int i = t; i < 202; i += TPB) {
        int v = s_hist[i];
        if (v) atomicAdd(&g_hist[i], v);
    }
}

// ---------------- kernel 3: finalize ----------------
__global__ void k_final(float* __restrict__ out, float invB) {
    int lane = threadIdx.x;
    float mc = fmaxf((float)g_hist[200], 1.0f);
    float fc = fmaxf((float)g_hist[201], 1.0f);
    float kl = 0.0f;
    for (int i = lane; i < 100; i += 32) {
        float p = (float)g_hist[i]       / mc;
        float q = (float)g_hist[100 + i] / fc;
        if (p > 0.0f && q > 0.0f) kl += p * logf(p / q);
    }
#pragma unroll
    for (int o = 16; o > 0; o >>= 1) kl += __shfl_xor_sync(0xffffffffu, kl, o);
    if (lane == 0) {
        float mse = g_part[0] * invB;
        float ce  = g_part[1] * invB;
        out[0] = 0.5f * (mse + ce) + 0.5f * kl;   // alpha = RATIO_KLD = 0.5
        out[1] = mse;
        out[2] = ce;
        out[3] = 0.5f * kl;
    }
}

// ---------------- launch ----------------
extern "C" void kernel_launch(void* const* d_in, const int* in_sizes, int n_in,
                              void* d_out, int out_size) {
    const float* enc = (const float*)d_in[0];   // [B,12]
    const float* dec = (const float*)d_in[1];   // [B,99]
    const float* tru = (const float*)d_in[2];   // [B,99]
    // d_in[3] (label_true) is numerically unused; d_in[4] (batch_size) unused.
    int B = in_sizes[1] / NC;

    cudaFuncSetAttribute(k_main, cudaFuncAttributeMaxDynamicSharedMemorySize, SMEM_BYTES);

    k_init<<<1, 256>>>();
    k_minmax<<<512, 256>>>(enc, B);
    k_main<<<B / RPB, TPB, SMEM_BYTES>>>(enc, dec, tru);
    k_final<<<1, 32>>>((float*)d_out, 1.0f / (float)B);
}

// round 2
// speedup vs baseline: 3.5135x; 3.5135x over previous
#include <cuda_runtime.h>
#include <math.h>

#define TPB 128
#define RPB 128          // rows per block tile
#define NC 99

// ---------------- scratch (device globals; no allocation) ----------------
__device__ unsigned int g_minmax[20];   // [0..9] min keys, [10..19] max keys
__device__ int          g_hist[202];    // [0..99] m, [100..199] f, [200]=m_count, [201]=f_count
__device__ double       g_part[2];      // [0]=mse_sum, [1]=ce_sum (lse - dot)

// monotonic float <-> uint key (total order preserved)
__device__ __forceinline__ unsigned fkey(float f) {
    unsigned u = __float_as_uint(f);
    return (u & 0x80000000u) ? ~u : (u | 0x80000000u);
}
__device__ __forceinline__ float kinv(unsigned k) {
    return __uint_as_float((k & 0x80000000u) ? (k & 0x7fffffffu) : ~k);
}

// ---------------- kernel 0: zero scratch (graph replay safe) ----------------
__global__ void k_init() {
    int t = threadIdx.x;
    if (t < 202) g_hist[t] = 0;
    if (t < 2)   g_part[t] = 0.0;
    if (t < 10)       g_minmax[t] = 0xFFFFFFFFu;   // min slots
    else if (t < 20)  g_minmax[t] = 0u;            // max slots
}

// ---------------- kernel 1: per-feature min/max over encoded[:, 0:10] ----------------
__global__ void k_minmax(const float* __restrict__ enc, int B) {
    float mn[10], mx[10];
#pragma unroll
    for (int f = 0; f < 10; f++) { mn[f] = INFINITY; mx[f] = -INFINITY; }

    int stride = gridDim.x * blockDim.x;
    for (int r = blockIdx.x * blockDim.x + threadIdx.x; r < B; r += stride) {
        const float4* p = (const float4*)(enc + (size_t)r * 12);
        float4 a = p[0], b = p[1], c = p[2];
        mn[0] = fminf(mn[0], a.x); mx[0] = fmaxf(mx[0], a.x);
        mn[1] = fminf(mn[1], a.y); mx[1] = fmaxf(mx[1], a.y);
        mn[2] = fminf(mn[2], a.z); mx[2] = fmaxf(mx[2], a.z);
        mn[3] = fminf(mn[3], a.w); mx[3] = fmaxf(mx[3], a.w);
        mn[4] = fminf(mn[4], b.x); mx[4] = fmaxf(mx[4], b.x);
        mn[5] = fminf(mn[5], b.y); mx[5] = fmaxf(mx[5], b.y);
        mn[6] = fminf(mn[6], b.z); mx[6] = fmaxf(mx[6], b.z);
        mn[7] = fminf(mn[7], b.w); mx[7] = fmaxf(mx[7], b.w);
        mn[8] = fminf(mn[8], c.x); mx[8] = fmaxf(mx[8], c.x);
        mn[9] = fminf(mn[9], c.y); mx[9] = fmaxf(mx[9], c.y);
    }
#pragma unroll
    for (int f = 0; f < 10; f++) {
#pragma unroll
        for (int o = 16; o > 0; o >>= 1) {
            mn[f] = fminf(mn[f], __shfl_xor_sync(0xffffffffu, mn[f], o));
            mx[f] = fmaxf(mx[f], __shfl_xor_sync(0xffffffffu, mx[f], o));
        }
    }
    __shared__ float smn[8][10], smx[8][10];
    int w = threadIdx.x >> 5, lane = threadIdx.x & 31;
    if (lane == 0) {
#pragma unroll
        for (int f = 0; f < 10; f++) { smn[w][f] = mn[f]; smx[w][f] = mx[f]; }
    }
    __syncthreads();
    if (threadIdx.x < 10) {
        int f = threadIdx.x;
        float a = INFINITY, b = -INFINITY;
#pragma unroll
        for (int ww = 0; ww < 8; ww++) { a = fminf(a, smn[ww][f]); b = fmaxf(b, smx[ww][f]); }
        atomicMin(&g_minmax[f],      fkey(a));
        atomicMax(&g_minmax[10 + f], fkey(b));
    }
}

// ---------------- kernel 2: fused MSE + CE + histograms ----------------
// smem: s_dec (RPB*NC floats) + s_hist (202 ints) + s_red (8 floats)
#define SMEM_BYTES (RPB*NC*4 + 202*4 + 8*4)

__global__ void __launch_bounds__(TPB, 4) k_main(const float* __restrict__ enc,
                                                 const float* __restrict__ dec,
                                                 const float* __restrict__ tru) {
    extern __shared__ float sm[];
    float* s_dec  = sm;
    int*   s_hist = (int*)(s_dec + RPB * NC);
    float* s_red  = (float*)(s_hist + 202);

    const int t = threadIdx.x;
    const size_t blk = blockIdx.x;

    for (int i = t; i < 202; i += TPB) s_hist[i] = 0;

    // ---- fused streaming pass: stash dec tile, accumulate dot (categorical)
    //      and mse (continuous cols 0,55,56,57) ----
    const float4* dsrc = (const float4*)(dec + blk * (RPB * NC));
    const float4* tsrc = (const float4*)(tru + blk * (RPB * NC));
    float4* sdec4 = (float4*)s_dec;

    float mse = 0.0f, dot = 0.0f;
    int c = (4 * t) % 99;                 // column of first element of this group
    for (int i = t; i < (RPB * NC) / 4; i += TPB) {
        float4 d4 = dsrc[i];
        sdec4[i] = d4;
        float4 t4 = tsrc[i];
        float dv[4] = {d4.x, d4.y, d4.z, d4.w};
        float tv[4] = {t4.x, t4.y, t4.z, t4.w};
#pragma unroll
        for (int j = 0; j < 4; j++) {
            int cc = c + j; if (cc >= 99) cc -= 99;
            bool cont = (cc == 0) | ((unsigned)(cc - 55) < 3u);
            if (cont) { float df = dv[j] - tv[j]; mse += df * df; }
            else      dot = fmaf(tv[j], dv[j], dot);
        }
        c += 17; if (c >= 99) c -= 99;    // (4*TPB) % 99 == 17
    }
    __syncthreads();

    // ---- per-row log-sum-exp over the 8 categorical blocks ----
    const int bs[8] = {1, 8, 24, 31, 45, 51, 53, 58};
    const int be[8] = {8, 24, 31, 45, 51, 53, 55, 99};
    const float* dr = &s_dec[t * NC];
    float lse = 0.0f;
#pragma unroll
    for (int b = 0; b < 8; b++) {
        float m = -INFINITY;
        for (int cix = bs[b]; cix < be[b]; cix++) m = fmaxf(m, dr[cix]);
        float sum = 0.0f;
        for (int cix = bs[b]; cix < be[b]; cix++) sum += __expf(dr[cix] - m);
        lse += m + __logf(sum);
    }
    float ce = lse - dot;

    // ---- histograms: read encoded row directly (coalesced: 48B/row contiguous) ----
    {
        const float4* ep = (const float4*)(enc + (blk * RPB + t) * 12);
        float4 e0 = ep[0], e1 = ep[1], e2 = ep[2];
        float fv[10] = {e0.x, e0.y, e0.z, e0.w, e1.x, e1.y, e1.z, e1.w, e2.x, e2.y};
        float sex = e2.w;
        int sel = (sex == 0.0f) ? 0 : ((sex == 1.0f) ? 1 : -1);
        if (sel >= 0) {
            atomicAdd(&s_hist[200 + sel], 1);
#pragma unroll
            for (int f = 0; f < 10; f++) {
                float mnv = kinv(g_minmax[f]);
                float mxv = kinv(g_minmax[10 + f]);
                float w   = fmaxf(__fsub_rn(mxv, mnv), 1e-12f);
                // match reference fp exactly: ((x - mn) / width) * 10, IEEE rn
                float u  = __fmul_rn(__fdiv_rn(__fsub_rn(fv[f], mnv), w), 10.0f);
                int bi = (int)floorf(u);
                bi = bi < 0 ? 0 : (bi > 9 ? 9 : bi);
                atomicAdd(&s_hist[sel * 100 + f * 10 + bi], 1);
            }
        }
    }

    // ---- block reduce mse/ce, flush hist ----
#pragma unroll
    for (int o = 16; o > 0; o >>= 1) {
        mse += __shfl_xor_sync(0xffffffffu, mse, o);
        ce  += __shfl_xor_sync(0xffffffffu, ce, o);
    }
    int w = t >> 5, lane = t & 31;
    if (lane == 0) { s_red[w] = mse; s_red[4 + w] = ce; }
    __syncthreads();
    if (t == 0) {
        atomicAdd(&g_part[0], (double)(s_red[0] + s_red[1] + s_red[2] + s_red[3]));
        atomicAdd(&g_part[1], (double)(s_red[4] + s_red[5] + s_red[6] + s_red[7]));
    }
    for (int i = t; i < 202; i += TPB) {
        int v = s_hist[i];
        if (v) atomicAdd(&g_hist[i], v);
    }
}

// ---------------- kernel 3: finalize ----------------
__global__ void k_final(float* __restrict__ out, float invB) {
    int lane = threadIdx.x;
    float mc = fmaxf((float)g_hist[200], 1.0f);
    float fc = fmaxf((float)g_hist[201], 1.0f);
    float kl = 0.0f;
    for (int i = lane; i < 100; i += 32) {
        float p = __fdiv_rn((float)g_hist[i],       mc);
        float q = __fdiv_rn((float)g_hist[100 + i], fc);
        if (p > 0.0f && q > 0.0f) kl += __fmul_rn(p, logf(__fdiv_rn(p, q)));
    }
#pragma unroll
    for (int o = 16; o > 0; o >>= 1) kl += __shfl_xor_sync(0xffffffffu, kl, o);
    if (lane == 0) {
        float mse = (float)(g_part[0] * (double)invB);
        float ce  = (float)(g_part[1] * (double)invB);
        out[0] = 0.5f * (mse + ce) + 0.5f * kl;   // alpha = RATIO_KLD = 0.5
        out[1] = mse;
        out[2] = ce;
        out[3] = 0.5f * kl;
    }
}

// ---------------- launch ----------------
extern "C" void kernel_launch(void* const* d_in, const int* in_sizes, int n_in,
                              void* d_out, int out_size) {
    const float* enc = (const float*)d_in[0];   // [B,12]
    const float* dec = (const float*)d_in[1];   // [B,99]
    const float* tru = (const float*)d_in[2];   // [B,99]
    // d_in[3] (label_true) numerically unused; d_in[4] (batch_size) unused.
    int B = in_sizes[1] / NC;

    cudaFuncSetAttribute(k_main, cudaFuncAttributeMaxDynamicSharedMemorySize, SMEM_BYTES);

    k_init<<<1, 256>>>();
    k_minmax<<<512, 256>>>(enc, B);
    k_main<<<B / RPB, TPB, SMEM_BYTES>>>(enc, dec, tru);
    k_final<<<1, 32>>>((float*)d_out, 1.0f / (float)B);
}